// round 3
// baseline (speedup 1.0000x reference)
#include <cuda_runtime.h>
#include <cuda_bf16.h>

// out[b,h,i,j] = in[b,h,i,j] + slope[h] * (j - (S-1)),  slope[h] = 2^(-0.5*(h+1))
// Shape: (2, 16, 2048, 2048) fp32. Pure HBM-streaming elementwise add.
//
// R3: VPT=8 (8 front-batched LDG.128 per thread -> MLP_p1=8), streaming
//     hints, grid 16384 blocks of 256.

static constexpr int SEQ = 2048;
static constexpr unsigned long long ROW_MASK = SEQ - 1;
static constexpr int HEAD_SHIFT = 22;        // 2048*2048 elems per head-plane
static constexpr int HEAD_MASK = 15;
static constexpr int VPT = 8;                // float4s per thread

__global__ void __launch_bounds__(256)
alibi_add_kernel(const float4* __restrict__ in, float4* __restrict__ out) {
    // Block covers contiguous 256*VPT float4s; thread t owns t + k*256.
    unsigned int base = blockIdx.x * (256u * VPT) + threadIdx.x;

    float4 v[VPT];
#pragma unroll
    for (int k = 0; k < VPT; k++) {
        v[k] = __ldcs(&in[base + k * 256u]);   // all 8 loads front-batched
    }

#pragma unroll
    for (int k = 0; k < VPT; k++) {
        unsigned int idx = base + k * 256u;
        unsigned long long e = (unsigned long long)idx * 4ull;
        int j = (int)(e & ROW_MASK);
        int h = (int)((e >> HEAD_SHIFT) & HEAD_MASK);

        float slope = exp2f(-0.5f * (float)(h + 1));
        float d0 = (float)(j - (SEQ - 1));

        float4 r = v[k];
        r.x = fmaf(slope, d0,        r.x);
        r.y = fmaf(slope, d0 + 1.0f, r.y);
        r.z = fmaf(slope, d0 + 2.0f, r.z);
        r.w = fmaf(slope, d0 + 3.0f, r.w);
        __stcs(&out[idx], r);                  // store drains while later FMAs run
    }
}

extern "C" void kernel_launch(void* const* d_in, const int* in_sizes, int n_in,
                              void* d_out, int out_size) {
    const float4* in = (const float4*)d_in[0];
    float4* out = (float4*)d_out;
    unsigned int n4 = (unsigned int)(out_size / 4);   // 33554432

    const int block = 256;
    unsigned int grid = n4 / (block * VPT);           // 16384 blocks (exact)
    alibi_add_kernel<<<grid, block>>>(in, out);
}